// round 4
// baseline (speedup 1.0000x reference)
#include <cuda_runtime.h>
#include <cstdint>

// QuantizationLayer: out[i*4 + {0..3}] = bits (MSB-first) of round_half_even(x[i]*16 - 0.5)
// x: (32768, 512) f32 in [0,1)  ->  out: (32768, 2048) f32 of {0.0, 1.0}
//
// Persistent CTAs; each tile of 1024 inputs is computed into a 16KB SMEM
// buffer and written to GMEM with ONE cp.async.bulk (TMA bulk store).
// Double-buffered so the bulk-store drain overlaps the next tile's
// loads/compute. Loads stay scalar+coalesced with streaming hint.

#define THREADS 256
#define TILE_IN 1024                     // inputs per tile
#define PER_THREAD (TILE_IN / THREADS)   // 4
#define TILE_OUT_BYTES (TILE_IN * 16)    // 16 KB per bulk store
#define GRID 1064                        // ~152 SMs * 7 CTAs: single persistent wave

__global__ void __launch_bounds__(THREADS)
quant_bulk_kernel(const float* __restrict__ x,
                  float* __restrict__ out,
                  int n_tiles) {
    __shared__ __align__(128) float4 sbuf[2][TILE_IN];

    const int tid = threadIdx.x;

    int it = 0;
    for (int t = blockIdx.x; t < n_tiles; t += gridDim.x, ++it) {
        const int buf = it & 1;
        const float* xin = x + (size_t)t * TILE_IN;

        // Issue loads first: overlaps with the bulk-store wait below.
        float v[PER_THREAD];
#pragma unroll
        for (int k = 0; k < PER_THREAD; k++)
            v[k] = __ldcs(xin + tid + k * THREADS);

        // Ensure the bulk store that last used this buffer has finished
        // reading SMEM (it was issued 2 iterations ago; keep <=1 pending).
        if (it >= 2 && tid == 0)
            asm volatile("cp.async.bulk.wait_group.read 1;" ::: "memory");
        __syncthreads();

#pragma unroll
        for (int k = 0; k < PER_THREAD; k++) {
            // round-half-to-even (rintf = RN nearest-even) matches jnp.round;
            // x*16 exact (pow2), -0.5 exact, code in [0,15].
            int c = ((int)rintf(fmaf(v[k], 16.0f, -0.5f))) & 15;
            float4 bits;
            bits.x = (float)((c >> 3) & 1);
            bits.y = (float)((c >> 2) & 1);
            bits.z = (float)((c >> 1) & 1);
            bits.w = (float)(c & 1);
            sbuf[buf][tid + k * THREADS] = bits;   // STS.128, conflict-free
        }

        // Order generic STS writes before async-proxy (TMA) reads.
        asm volatile("fence.proxy.async.shared::cta;" ::: "memory");
        __syncthreads();

        if (tid == 0) {
            uint32_t saddr;
            asm("{ .reg .u64 tt; cvta.to.shared.u64 tt, %1; cvt.u32.u64 %0, tt; }"
                : "=r"(saddr) : "l"(&sbuf[buf][0]));
            uint64_t gaddr = (uint64_t)out + (uint64_t)t * TILE_OUT_BYTES;
            int nbytes = TILE_OUT_BYTES;
            asm volatile(
                "cp.async.bulk.global.shared::cta.bulk_group [%0], [%1], %2;\n\t"
                "cp.async.bulk.commit_group;"
                :: "l"(gaddr), "r"(saddr), "r"(nbytes) : "memory");
        }
        // No extra sync needed here: buffer reuse is gated by the
        // wait_group + __syncthreads at the top of the loop.
    }

    // SMEM must stay valid until all bulk stores complete.
    if (tid == 0)
        asm volatile("cp.async.bulk.wait_group.read 0;" ::: "memory");
}

// Scalar fallback for any remainder elements (not taken for n = 16,777,216).
__global__ void quant_tail_kernel(const float* __restrict__ x,
                                  float4* __restrict__ out,
                                  int start, int n) {
    int i = start + blockIdx.x * blockDim.x + threadIdx.x;
    if (i >= n) return;
    int c = ((int)rintf(fmaf(x[i], 16.0f, -0.5f))) & 15;
    float4 bits;
    bits.x = (float)((c >> 3) & 1);
    bits.y = (float)((c >> 2) & 1);
    bits.z = (float)((c >> 1) & 1);
    bits.w = (float)(c & 1);
    out[i] = bits;
}

extern "C" void kernel_launch(void* const* d_in, const int* in_sizes, int n_in,
                              void* d_out, int out_size) {
    const float* x = (const float*)d_in[0];
    float* out = (float*)d_out;
    int n = in_sizes[0];                 // 16,777,216

    int n_tiles = n / TILE_IN;           // 16384
    int grid = (n_tiles < GRID) ? n_tiles : GRID;
    if (grid > 0)
        quant_bulk_kernel<<<grid, THREADS>>>(x, out, n_tiles);

    int done = n_tiles * TILE_IN;
    int rem = n - done;
    if (rem > 0) {
        int tb = 256;
        quant_tail_kernel<<<(rem + tb - 1) / tb, tb>>>(x, (float4*)out, done, n);
    }
}

// round 5
// speedup vs baseline: 1.2131x; 1.2131x over previous
#include <cuda_runtime.h>
#include <cstdint>

// QuantizationLayer: out[i*4 + {0..3}] = bits (MSB-first) of round_half_even(x[i]*16 - 0.5)
// x: (32768, 512) f32 in [0,1)  ->  out: (32768, 2048) f32 of {0.0, 1.0}
//
// Streaming kernel. Each thread handles 2 adjacent input elements per step
// (float2 load = 256B/warp; one 256-bit v8 store = 1024B/warp), 2 steps per
// thread (4 elements total - the R1 optimum). Streaming cache hints on both
// directions (read-once / write-once).

#define THREADS 256
#define PAIRS_PER_THREAD 2                      // 2 pairs = 4 elements/thread
#define TILE_PAIRS (THREADS * PAIRS_PER_THREAD) // 512 pairs = 1024 elems/block

__device__ __forceinline__ void quant_pair_store(float2 v, float* gptr) {
    // codes for the two elements
    int c0 = ((int)rintf(fmaf(v.x, 16.0f, -0.5f))) & 15;
    int c1 = ((int)rintf(fmaf(v.y, 16.0f, -0.5f))) & 15;

    float b0 = (float)((c0 >> 3) & 1);
    float b1 = (float)((c0 >> 2) & 1);
    float b2 = (float)((c0 >> 1) & 1);
    float b3 = (float)(c0 & 1);
    float b4 = (float)((c1 >> 3) & 1);
    float b5 = (float)((c1 >> 2) & 1);
    float b6 = (float)((c1 >> 1) & 1);
    float b7 = (float)(c1 & 1);

#if __CUDA_ARCH__ >= 1000
    asm volatile(
        "st.global.cs.v8.f32 [%0], {%1, %2, %3, %4, %5, %6, %7, %8};"
        :: "l"(gptr),
           "f"(b0), "f"(b1), "f"(b2), "f"(b3),
           "f"(b4), "f"(b5), "f"(b6), "f"(b7)
        : "memory");
#else
    float4 lo = make_float4(b0, b1, b2, b3);
    float4 hi = make_float4(b4, b5, b6, b7);
    __stcs((float4*)gptr, lo);
    __stcs((float4*)gptr + 1, hi);
#endif
}

__global__ void __launch_bounds__(THREADS)
quant_unpack_kernel(const float2* __restrict__ x2,
                    float* __restrict__ out,
                    int n_pairs) {
    int base = blockIdx.x * TILE_PAIRS + threadIdx.x;

    if (base + (PAIRS_PER_THREAD - 1) * THREADS < n_pairs) {
        // Fast path (always taken for n = 16,777,216): no per-element guards.
        float2 v[PAIRS_PER_THREAD];
#pragma unroll
        for (int k = 0; k < PAIRS_PER_THREAD; k++)
            v[k] = __ldcs(x2 + base + k * THREADS);

#pragma unroll
        for (int k = 0; k < PAIRS_PER_THREAD; k++) {
            int p = base + k * THREADS;
            quant_pair_store(v[k], out + (size_t)p * 8);
        }
    } else {
        // Tail path
#pragma unroll
        for (int k = 0; k < PAIRS_PER_THREAD; k++) {
            int p = base + k * THREADS;
            if (p >= n_pairs) continue;
            float2 v = __ldcs(x2 + p);
            quant_pair_store(v, out + (size_t)p * 8);
        }
    }
}

extern "C" void kernel_launch(void* const* d_in, const int* in_sizes, int n_in,
                              void* d_out, int out_size) {
    const float* x = (const float*)d_in[0];
    float* out = (float*)d_out;
    int n = in_sizes[0];        // 16,777,216 (even, so pairs are exact)
    int n_pairs = n >> 1;       // 8,388,608

    int blocks = (n_pairs + TILE_PAIRS - 1) / TILE_PAIRS;  // 16384
    quant_unpack_kernel<<<blocks, THREADS>>>((const float2*)x, out, n_pairs);
}

// round 6
// speedup vs baseline: 1.2204x; 1.0060x over previous
#include <cuda_runtime.h>
#include <cstdint>

// QuantizationLayer: out[i*4 + {0..3}] = bits (MSB-first) of round_half_even(x[i]*16 - 0.5)
// x: (32768, 512) f32 in [0,1)  ->  out: (32768, 2048) f32 of {0.0, 1.0}
//
// Streaming kernel. Each thread handles 2 adjacent input elements per step
// (float2 load = 256B/warp; one 256-bit v8 store = 1024B/warp), 2 steps
// per thread. Loads use .cs (read-once, evict-first). Stores use DEFAULT
// write-back policy: let the 126MB L2 accumulate large dirty regions and
// drain them to DRAM in long row-hit bursts (vs .cs evict-first, which
// forces small scattered write bursts).

#define THREADS 256
#define PAIRS_PER_THREAD 2                      // 2 pairs = 4 elements/thread
#define TILE_PAIRS (THREADS * PAIRS_PER_THREAD) // 512 pairs = 1024 elems/block

__device__ __forceinline__ void quant_pair_store(float2 v, float* gptr) {
    int c0 = ((int)rintf(fmaf(v.x, 16.0f, -0.5f))) & 15;
    int c1 = ((int)rintf(fmaf(v.y, 16.0f, -0.5f))) & 15;

    float b0 = (float)((c0 >> 3) & 1);
    float b1 = (float)((c0 >> 2) & 1);
    float b2 = (float)((c0 >> 1) & 1);
    float b3 = (float)(c0 & 1);
    float b4 = (float)((c1 >> 3) & 1);
    float b5 = (float)((c1 >> 2) & 1);
    float b6 = (float)((c1 >> 1) & 1);
    float b7 = (float)(c1 & 1);

#if __CUDA_ARCH__ >= 1000
    // default write-back policy (no .cs)
    asm volatile(
        "st.global.v8.f32 [%0], {%1, %2, %3, %4, %5, %6, %7, %8};"
        :: "l"(gptr),
           "f"(b0), "f"(b1), "f"(b2), "f"(b3),
           "f"(b4), "f"(b5), "f"(b6), "f"(b7)
        : "memory");
#else
    float4 lo = make_float4(b0, b1, b2, b3);
    float4 hi = make_float4(b4, b5, b6, b7);
    ((float4*)gptr)[0] = lo;
    ((float4*)gptr)[1] = hi;
#endif
}

__global__ void __launch_bounds__(THREADS)
quant_unpack_kernel(const float2* __restrict__ x2,
                    float* __restrict__ out,
                    int n_pairs) {
    int base = blockIdx.x * TILE_PAIRS + threadIdx.x;

    if (base + (PAIRS_PER_THREAD - 1) * THREADS < n_pairs) {
        // Fast path (always taken for n = 16,777,216)
        float2 v[PAIRS_PER_THREAD];
#pragma unroll
        for (int k = 0; k < PAIRS_PER_THREAD; k++)
            v[k] = __ldcs(x2 + base + k * THREADS);

#pragma unroll
        for (int k = 0; k < PAIRS_PER_THREAD; k++) {
            int p = base + k * THREADS;
            quant_pair_store(v[k], out + (size_t)p * 8);
        }
    } else {
        // Tail path
#pragma unroll
        for (int k = 0; k < PAIRS_PER_THREAD; k++) {
            int p = base + k * THREADS;
            if (p >= n_pairs) continue;
            float2 v = __ldcs(x2 + p);
            quant_pair_store(v, out + (size_t)p * 8);
        }
    }
}

extern "C" void kernel_launch(void* const* d_in, const int* in_sizes, int n_in,
                              void* d_out, int out_size) {
    const float* x = (const float*)d_in[0];
    float* out = (float*)d_out;
    int n = in_sizes[0];        // 16,777,216 (even)
    int n_pairs = n >> 1;       // 8,388,608

    int blocks = (n_pairs + TILE_PAIRS - 1) / TILE_PAIRS;  // 16384
    quant_unpack_kernel<<<blocks, THREADS>>>((const float2*)x, out, n_pairs);
}